// round 2
// baseline (speedup 1.0000x reference)
#include <cuda_runtime.h>

#define B_      2
#define C_      192
#define C3_     576
#define H_      256
#define W_      256
#define HW_     65536
#define HEADS_  8
#define SLICE_  8192
#define KSPLIT_ 8

// ---------------- scratch (device globals: allocation-free rule) ----------------
__device__ float g_qkv  [(size_t)B_ * C3_ * HW_];                     // 1x1 conv out
__device__ float g_qkvdw[(size_t)B_ * C3_ * HW_];                     // depthwise out
__device__ float g_av   [(size_t)B_ * C_ * HW_];                      // attn @ v
__device__ float g_gramp[(size_t)KSPLIT_ * B_ * HEADS_ * C_ * C_];    // split-K partials
__device__ float g_attn [(size_t)B_ * HEADS_ * C_ * C_];              // softmaxed attn
__device__ float g_invq [B_ * C_ * 8];
__device__ float g_invk [B_ * C_ * 8];

// =====================================================================
// 128x128 BK=16 double-buffered SGEMM, 256 threads, 8x8 microtile.
// Map provides row pointers; all B/C rows contiguous along n.
// =====================================================================
struct QkvMap {
    const float* A; const float* B; float* C;
    __device__ const float* aRow(int z, int m) const { return A + (long long)min(m, C3_ - 1) * C_; }
    __device__ const float* bRow(int z, int k) const { return B + ((long long)z * C_ + k) * (long long)HW_; }
    __device__ float*       cRow(int z, int m) const { return C + ((long long)z * C3_ + m) * (long long)HW_; }
    __device__ int mMax() const { return C3_; }
};
struct AvMap {
    const float* A; const float* B; float* C;   // A=attn, B=qkvdw(v part), C=av
    __device__ const float* aRow(int z, int m) const { return A + (long long)z * (C_ * C_) + min(m, C_ - 1) * C_; }
    __device__ const float* bRow(int z, int k) const {
        int b = z >> 3, h = z & 7;
        return B + ((long long)(b * C3_ + 2 * C_ + h * 24 + (k >> 3)) << 16) + ((k & 7) << 13);
    }
    __device__ float* cRow(int z, int m) const {
        int b = z >> 3, h = z & 7;
        return C + ((long long)(b * C_ + h * 24 + (m >> 3)) << 16) + ((m & 7) << 13);
    }
    __device__ int mMax() const { return C_; }
};
struct ProjMap {
    const float* A; const float* B; float* C;
    __device__ const float* aRow(int z, int m) const { return A + (long long)min(m, C_ - 1) * C_; }
    __device__ const float* bRow(int z, int k) const { return B + ((long long)z * C_ + k) * (long long)HW_; }
    __device__ float*       cRow(int z, int m) const { return C + ((long long)z * C_ + m) * (long long)HW_; }
    __device__ int mMax() const { return C_; }
};

template <class Map>
__global__ __launch_bounds__(256, 2) void gemm128(Map map, int K)
{
    __shared__ float As[2][16][128];
    __shared__ float Bs[2][16][128];

    const int z = blockIdx.z;
    const int bm = blockIdx.y * 128, bn = blockIdx.x * 128;
    const int tid = threadIdx.x;
    const int tx = tid & 15, ty = tid >> 4;

    const int arow = tid >> 1, ak = (tid & 1) << 3;     // A loader: row, k-offset
    const int bkr = tid >> 4, bnc = (tid & 15) << 3;    // B loader: k-row, n-offset

    const float* aRowPtr = map.aRow(z, bm + arow);

    float4 a0r = *(const float4*)(aRowPtr + ak);
    float4 a1r = *(const float4*)(aRowPtr + ak + 4);
    float4 b0r, b1r;
    {
        const float* bp = map.bRow(z, bkr) + bn + bnc;
        b0r = *(const float4*)bp;
        b1r = *(const float4*)(bp + 4);
    }

    As[0][ak + 0][arow] = a0r.x; As[0][ak + 1][arow] = a0r.y;
    As[0][ak + 2][arow] = a0r.z; As[0][ak + 3][arow] = a0r.w;
    As[0][ak + 4][arow] = a1r.x; As[0][ak + 5][arow] = a1r.y;
    As[0][ak + 6][arow] = a1r.z; As[0][ak + 7][arow] = a1r.w;
    *(float4*)&Bs[0][bkr][bnc]     = b0r;
    *(float4*)&Bs[0][bkr][bnc + 4] = b1r;
    __syncthreads();

    float acc[8][8];
#pragma unroll
    for (int i = 0; i < 8; ++i)
#pragma unroll
        for (int j = 0; j < 8; ++j) acc[i][j] = 0.f;

    const int nStage = K >> 4;
    int buf = 0;
#pragma unroll 1
    for (int s = 0; s < nStage; ++s) {
        if (s + 1 < nStage) {
            const int kt = (s + 1) << 4;
            a0r = *(const float4*)(aRowPtr + kt + ak);
            a1r = *(const float4*)(aRowPtr + kt + ak + 4);
            const float* bp = map.bRow(z, kt + bkr) + bn + bnc;
            b0r = *(const float4*)bp;
            b1r = *(const float4*)(bp + 4);
        }
#pragma unroll
        for (int k = 0; k < 16; ++k) {
            float a[8], b[8];
            *(float4*)&a[0] = *(const float4*)&As[buf][k][ty << 3];
            *(float4*)&a[4] = *(const float4*)&As[buf][k][(ty << 3) + 4];
            *(float4*)&b[0] = *(const float4*)&Bs[buf][k][tx << 3];
            *(float4*)&b[4] = *(const float4*)&Bs[buf][k][(tx << 3) + 4];
#pragma unroll
            for (int i = 0; i < 8; ++i)
#pragma unroll
                for (int j = 0; j < 8; ++j) acc[i][j] += a[i] * b[j];
        }
        if (s + 1 < nStage) {
            buf ^= 1;
            As[buf][ak + 0][arow] = a0r.x; As[buf][ak + 1][arow] = a0r.y;
            As[buf][ak + 2][arow] = a0r.z; As[buf][ak + 3][arow] = a0r.w;
            As[buf][ak + 4][arow] = a1r.x; As[buf][ak + 5][arow] = a1r.y;
            As[buf][ak + 6][arow] = a1r.z; As[buf][ak + 7][arow] = a1r.w;
            *(float4*)&Bs[buf][bkr][bnc]     = b0r;
            *(float4*)&Bs[buf][bkr][bnc + 4] = b1r;
        }
        __syncthreads();
    }

#pragma unroll
    for (int i = 0; i < 8; ++i) {
        const int m = bm + (ty << 3) + i;
        if (m < map.mMax()) {
            float* c = map.cRow(z, m) + bn + (tx << 3);
            *(float4*)c       = make_float4(acc[i][0], acc[i][1], acc[i][2], acc[i][3]);
            *(float4*)(c + 4) = make_float4(acc[i][4], acc[i][5], acc[i][6], acc[i][7]);
        }
    }
}

// =====================================================================
// Gram (A·B^T): C[i,j] = sum_n q[i,n]*k[j,n], split-K=8, 128x128 tiles
// =====================================================================
__global__ __launch_bounds__(256, 2) void gram128(
    const float* __restrict__ qkvdw, float* __restrict__ gramp)
{
    const int z = blockIdx.z;
    const int ks = z & 7, bh = z >> 3;
    const int h = bh & 7, b = bh >> 3;
    const int bi = blockIdx.y * 128, bj = blockIdx.x * 128;

    __shared__ float Qs[2][16][128];
    __shared__ float Ks[2][16][128];

    const int tid = threadIdx.x;
    const int tx = tid & 15, ty = tid >> 4;
    const int lr = tid >> 1, lk = (tid & 1) << 3;

    const int qi = min(bi + lr, C_ - 1);
    const int kj = min(bj + lr, C_ - 1);
    const float* qrow = qkvdw + ((long long)(b * C3_ + h * 24 + (qi >> 3)) << 16) + ((qi & 7) << 13) + ks * 1024 + lk;
    const float* krow = qkvdw + ((long long)(b * C3_ + C_ + h * 24 + (kj >> 3)) << 16) + ((kj & 7) << 13) + ks * 1024 + lk;

    float4 q0 = *(const float4*)qrow,       q1 = *(const float4*)(qrow + 4);
    float4 k0 = *(const float4*)krow,       k1 = *(const float4*)(krow + 4);

    Qs[0][lk + 0][lr] = q0.x; Qs[0][lk + 1][lr] = q0.y; Qs[0][lk + 2][lr] = q0.z; Qs[0][lk + 3][lr] = q0.w;
    Qs[0][lk + 4][lr] = q1.x; Qs[0][lk + 5][lr] = q1.y; Qs[0][lk + 6][lr] = q1.z; Qs[0][lk + 7][lr] = q1.w;
    Ks[0][lk + 0][lr] = k0.x; Ks[0][lk + 1][lr] = k0.y; Ks[0][lk + 2][lr] = k0.z; Ks[0][lk + 3][lr] = k0.w;
    Ks[0][lk + 4][lr] = k1.x; Ks[0][lk + 5][lr] = k1.y; Ks[0][lk + 6][lr] = k1.z; Ks[0][lk + 7][lr] = k1.w;
    __syncthreads();

    float acc[8][8];
#pragma unroll
    for (int i = 0; i < 8; ++i)
#pragma unroll
        for (int j = 0; j < 8; ++j) acc[i][j] = 0.f;

    int buf = 0;
#pragma unroll 1
    for (int s = 0; s < 64; ++s) {               // K = 1024, BK = 16
        if (s + 1 < 64) {
            const int kt = (s + 1) << 4;
            q0 = *(const float4*)(qrow + kt);     q1 = *(const float4*)(qrow + kt + 4);
            k0 = *(const float4*)(krow + kt);     k1 = *(const float4*)(krow + kt + 4);
        }
#pragma unroll
        for (int k = 0; k < 16; ++k) {
            float a[8], bb[8];
            *(float4*)&a[0]  = *(const float4*)&Qs[buf][k][ty << 3];
            *(float4*)&a[4]  = *(const float4*)&Qs[buf][k][(ty << 3) + 4];
            *(float4*)&bb[0] = *(const float4*)&Ks[buf][k][tx << 3];
            *(float4*)&bb[4] = *(const float4*)&Ks[buf][k][(tx << 3) + 4];
#pragma unroll
            for (int i = 0; i < 8; ++i)
#pragma unroll
                for (int j = 0; j < 8; ++j) acc[i][j] += a[i] * bb[j];
        }
        if (s + 1 < 64) {
            buf ^= 1;
            Qs[buf][lk + 0][lr] = q0.x; Qs[buf][lk + 1][lr] = q0.y; Qs[buf][lk + 2][lr] = q0.z; Qs[buf][lk + 3][lr] = q0.w;
            Qs[buf][lk + 4][lr] = q1.x; Qs[buf][lk + 5][lr] = q1.y; Qs[buf][lk + 6][lr] = q1.z; Qs[buf][lk + 7][lr] = q1.w;
            Ks[buf][lk + 0][lr] = k0.x; Ks[buf][lk + 1][lr] = k0.y; Ks[buf][lk + 2][lr] = k0.z; Ks[buf][lk + 3][lr] = k0.w;
            Ks[buf][lk + 4][lr] = k1.x; Ks[buf][lk + 5][lr] = k1.y; Ks[buf][lk + 6][lr] = k1.z; Ks[buf][lk + 7][lr] = k1.w;
        }
        __syncthreads();
    }

    if (bj + (tx << 3) + 7 < C_) {
        const long long obase = ((long long)ks * (B_ * HEADS_) + bh) * (C_ * C_);
#pragma unroll
        for (int i = 0; i < 8; ++i) {
            const int im = bi + (ty << 3) + i;
            if (im < C_) {
                float* op = gramp + obase + (long long)im * C_ + bj + (tx << 3);
                *(float4*)op       = make_float4(acc[i][0], acc[i][1], acc[i][2], acc[i][3]);
                *(float4*)(op + 4) = make_float4(acc[i][4], acc[i][5], acc[i][6], acc[i][7]);
            }
        }
    }
}

// ---------------- depthwise 3x3, SAME padding --------------------------------
__global__ __launch_bounds__(256) void dw_kernel(
    const float* __restrict__ in_, const float* __restrict__ dww, float* __restrict__ out_)
{
    const int chg = blockIdx.z;            // b*576 + c
    const int c = chg % C3_;
    const float* in = in_ + ((long long)chg << 16);
    float* op = out_ + ((long long)chg << 16);

    float w[9];
#pragma unroll
    for (int i = 0; i < 9; ++i) w[i] = __ldg(&dww[c * 9 + i]);

    __shared__ float s[34][34];
    const int ox = blockIdx.x * 32 - 1, oy = blockIdx.y * 32 - 1;
    for (int t = threadIdx.x; t < 34 * 34; t += 256) {
        int lx = t % 34, ly = t / 34;
        int gx = ox + lx, gy = oy + ly;
        float v = 0.f;
        if ((unsigned)gx < W_ && (unsigned)gy < H_) v = in[gy * W_ + gx];
        s[ly][lx] = v;
    }
    __syncthreads();

    const int tx = threadIdx.x & 31, ty0 = threadIdx.x >> 5;
#pragma unroll
    for (int r = 0; r < 4; ++r) {
        int ly = ty0 + 8 * r;
        float acc = s[ly + 0][tx + 0] * w[0] + s[ly + 0][tx + 1] * w[1] + s[ly + 0][tx + 2] * w[2]
                  + s[ly + 1][tx + 0] * w[3] + s[ly + 1][tx + 1] * w[4] + s[ly + 1][tx + 2] * w[5]
                  + s[ly + 2][tx + 0] * w[6] + s[ly + 2][tx + 1] * w[7] + s[ly + 2][tx + 2] * w[8];
        op[(blockIdx.y * 32 + ly) * W_ + blockIdx.x * 32 + tx] = acc;
    }
}

// ---------------- per-slice L2 norms of q and k -------------------------------
__global__ __launch_bounds__(256) void norms_kernel(
    const float* __restrict__ qkvdw, float* __restrict__ invq, float* __restrict__ invk)
{
    const int z = blockIdx.x;              // b*192*8 + ch*8 + sl
    const int sl = z & 7;
    const int ch = (z >> 3) % C_;
    const int b = z / (C_ * 8);
    const float4* qp = (const float4*)(qkvdw + ((long long)(b * C3_ + ch) << 16) + (sl << 13));
    const float4* kp = (const float4*)(qkvdw + ((long long)(b * C3_ + C_ + ch) << 16) + (sl << 13));

    float sq = 0.f, sk = 0.f;
    for (int t = threadIdx.x; t < SLICE_ / 4; t += 256) {
        float4 v = qp[t]; sq += v.x * v.x + v.y * v.y + v.z * v.z + v.w * v.w;
        float4 w = kp[t]; sk += w.x * w.x + w.y * w.y + w.z * w.z + w.w * w.w;
    }
#pragma unroll
    for (int o = 16; o > 0; o >>= 1) {
        sq += __shfl_xor_sync(0xffffffffu, sq, o);
        sk += __shfl_xor_sync(0xffffffffu, sk, o);
    }
    __shared__ float r1[8], r2[8];
    if ((threadIdx.x & 31) == 0) { r1[threadIdx.x >> 5] = sq; r2[threadIdx.x >> 5] = sk; }
    __syncthreads();
    if (threadIdx.x == 0) {
        float a = 0.f, c2 = 0.f;
#pragma unroll
        for (int w2 = 0; w2 < 8; ++w2) { a += r1[w2]; c2 += r2[w2]; }
        int idx = (b * C_ + ch) * 8 + sl;
        invq[idx] = 1.f / fmaxf(sqrtf(a), 1e-12f);
        invk[idx] = 1.f / fmaxf(sqrtf(c2), 1e-12f);
    }
}

// ---------------- split-K reduce + normalize scales + softmax -----------------
__global__ void softmax_kernel(
    const float* __restrict__ gramp, const float* __restrict__ invq,
    const float* __restrict__ invk, const float* __restrict__ temp,
    float* __restrict__ attn)
{
    const int i = blockIdx.x % C_;
    const int bh = blockIdx.x / C_;
    const int head = bh & 7, b = bh >> 3;
    const int j = threadIdx.x;              // 192 threads

    const long long base = (long long)bh * (C_ * C_) + i * C_ + j;
    float s = 0.f;
#pragma unroll
    for (int ks = 0; ks < KSPLIT_; ++ks)
        s += gramp[(long long)ks * (B_ * HEADS_ * C_ * C_) + base];

    s *= invq[(b * C_ + head * 24 + (i >> 3)) * 8 + (i & 7)]
       * invk[(b * C_ + head * 24 + (j >> 3)) * 8 + (j & 7)]
       * temp[head];

    __shared__ float red[8];
    float m = s;
#pragma unroll
    for (int o = 16; o > 0; o >>= 1) m = fmaxf(m, __shfl_xor_sync(0xffffffffu, m, o));
    if ((threadIdx.x & 31) == 0) red[threadIdx.x >> 5] = m;
    __syncthreads();
    m = fmaxf(fmaxf(fmaxf(red[0], red[1]), fmaxf(red[2], red[3])), fmaxf(red[4], red[5]));

    float p = expf(s - m);
    float sum = p;
#pragma unroll
    for (int o = 16; o > 0; o >>= 1) sum += __shfl_xor_sync(0xffffffffu, sum, o);
    __syncthreads();
    if ((threadIdx.x & 31) == 0) red[threadIdx.x >> 5] = sum;
    __syncthreads();
    sum = red[0] + red[1] + red[2] + red[3] + red[4] + red[5];

    attn[base] = p / sum;
}

// ---------------- launch -------------------------------------------------------
extern "C" void kernel_launch(void* const* d_in, const int* in_sizes, int n_in,
                              void* d_out, int out_size)
{
    const float* x      = (const float*)d_in[0];
    const float* qkv_w  = (const float*)d_in[1];
    const float* dw_w   = (const float*)d_in[2];
    const float* proj_w = (const float*)d_in[3];
    const float* temp   = (const float*)d_in[4];
    float* out = (float*)d_out;

    float *qkv, *qkvdw, *av, *gramp, *attn, *invq, *invk;
    cudaGetSymbolAddress((void**)&qkv,   g_qkv);
    cudaGetSymbolAddress((void**)&qkvdw, g_qkvdw);
    cudaGetSymbolAddress((void**)&av,    g_av);
    cudaGetSymbolAddress((void**)&gramp, g_gramp);
    cudaGetSymbolAddress((void**)&attn,  g_attn);
    cudaGetSymbolAddress((void**)&invq,  g_invq);
    cudaGetSymbolAddress((void**)&invk,  g_invk);

    // 1) qkv = qkv_w @ x      [576,192] @ [192,65536] per batch
    {
        QkvMap m{qkv_w, x, qkv};
        gemm128<QkvMap><<<dim3(HW_ / 128, 5, B_), 256>>>(m, C_);
    }

    // 2) depthwise 3x3
    dw_kernel<<<dim3(W_ / 32, H_ / 32, B_ * C3_), 256>>>(qkv, dw_w, qkvdw);

    // 3) per-slice L2 norms of q and k
    norms_kernel<<<B_ * C_ * 8, 256>>>(qkvdw, invq, invk);

    // 4) Gram partials (split-K = 8)
    gram128<<<dim3(2, 2, B_ * HEADS_ * KSPLIT_), 256>>>(qkvdw, gramp);

    // 5) reduce + scale + softmax
    softmax_kernel<<<B_ * HEADS_ * C_, C_>>>(gramp, invq, invk, temp, attn);

    // 6) attn @ v
    {
        AvMap m{attn, qkvdw, av};
        gemm128<AvMap><<<dim3(SLICE_ / 128, 2, B_ * HEADS_), 256>>>(m, C_);
    }

    // 7) out = proj_w @ av     [192,192] @ [192,65536] per batch
    {
        ProjMap m{proj_w, av, out};
        gemm128<ProjMap><<<dim3(HW_ / 128, 2, B_), 256>>>(m, C_);
    }
}

// round 3
// speedup vs baseline: 2.1177x; 2.1177x over previous
#include <cuda_runtime.h>
#include <cuda_bf16.h>
#include <cstdint>

#define B_      2
#define C_      192
#define C3_     576
#define H_      256
#define W_      256
#define HW_     65536
#define HEADS_  8
#define KSPLIT_ 8

// ---------------- scratch (device globals: allocation-free rule) ----------------
__device__ __nv_bfloat16 g_qkvh [(size_t)B_ * C3_ * HW_];
__device__ __nv_bfloat16 g_qkvl [(size_t)B_ * C3_ * HW_];
__device__ __nv_bfloat16 g_dwh  [(size_t)B_ * C3_ * HW_];
__device__ __nv_bfloat16 g_dwl  [(size_t)B_ * C3_ * HW_];
__device__ __nv_bfloat16 g_avh  [(size_t)B_ * C_ * HW_];
__device__ __nv_bfloat16 g_avl  [(size_t)B_ * C_ * HW_];
__device__ float g_gramp[(size_t)KSPLIT_ * B_ * HEADS_ * C_ * C_];
__device__ float g_attn [(size_t)B_ * HEADS_ * C_ * C_];
__device__ float g_invq [B_ * C_ * 8];
__device__ float g_invk [B_ * C_ * 8];

// ---------------- mma / ldmatrix helpers ----------------
__device__ __forceinline__ void ldsm4(unsigned* r, const void* p) {
    unsigned a = (unsigned)__cvta_generic_to_shared(p);
    asm volatile("ldmatrix.sync.aligned.m8n8.x4.shared.b16 {%0,%1,%2,%3}, [%4];"
                 : "=r"(r[0]), "=r"(r[1]), "=r"(r[2]), "=r"(r[3]) : "r"(a));
}
__device__ __forceinline__ void ldsm2t(unsigned* r, const void* p) {
    unsigned a = (unsigned)__cvta_generic_to_shared(p);
    asm volatile("ldmatrix.sync.aligned.m8n8.x2.trans.shared.b16 {%0,%1}, [%2];"
                 : "=r"(r[0]), "=r"(r[1]) : "r"(a));
}
__device__ __forceinline__ void ldsm2(unsigned* r, const void* p) {
    unsigned a = (unsigned)__cvta_generic_to_shared(p);
    asm volatile("ldmatrix.sync.aligned.m8n8.x2.shared.b16 {%0,%1}, [%2];"
                 : "=r"(r[0]), "=r"(r[1]) : "r"(a));
}
__device__ __forceinline__ void mma16816(float* c, const unsigned* a, const unsigned* b) {
    asm volatile("mma.sync.aligned.m16n8k16.row.col.f32.bf16.bf16.f32 "
                 "{%0,%1,%2,%3},{%4,%5,%6,%7},{%8,%9},{%0,%1,%2,%3};"
                 : "+f"(c[0]), "+f"(c[1]), "+f"(c[2]), "+f"(c[3])
                 : "r"(a[0]), "r"(a[1]), "r"(a[2]), "r"(a[3]), "r"(b[0]), "r"(b[1]));
}

__device__ __forceinline__ void stsplit(__nv_bfloat16* ph, __nv_bfloat16* pl, float4 v) {
    __nv_bfloat16 h0 = __float2bfloat16(v.x), h1 = __float2bfloat16(v.y);
    __nv_bfloat16 h2 = __float2bfloat16(v.z), h3 = __float2bfloat16(v.w);
    __nv_bfloat162 t;
    t.x = h0; t.y = h1; ((__nv_bfloat162*)ph)[0] = t;
    t.x = h2; t.y = h3; ((__nv_bfloat162*)ph)[1] = t;
    t.x = __float2bfloat16(v.x - __bfloat162float(h0));
    t.y = __float2bfloat16(v.y - __bfloat162float(h1)); ((__nv_bfloat162*)pl)[0] = t;
    t.x = __float2bfloat16(v.z - __bfloat162float(h2));
    t.y = __float2bfloat16(v.w - __bfloat162float(h3)); ((__nv_bfloat162*)pl)[1] = t;
}
__device__ __forceinline__ void st_pair(__nv_bfloat16* ph, __nv_bfloat16* pl, float x, float y) {
    __nv_bfloat16 hx = __float2bfloat16(x), hy = __float2bfloat16(y);
    __nv_bfloat162 hp; hp.x = hx; hp.y = hy; *(__nv_bfloat162*)ph = hp;
    __nv_bfloat162 lp;
    lp.x = __float2bfloat16(x - __bfloat162float(hx));
    lp.y = __float2bfloat16(y - __bfloat162float(hy));
    *(__nv_bfloat162*)pl = lp;
}

// ---------------- maps for the three n-wide GEMMs ----------------
struct QkvMap {
    const float* A; const float* B; __nv_bfloat16 *Ch, *Cl;
    static constexpr bool B_BF16 = false, C_BF16 = true;
    __device__ const float* aRow(int z, int m) const { return A + (size_t)m * C_; }
    __device__ const float* bRow(int z, int k) const { return B + ((size_t)z * C_ + k) * HW_; }
    __device__ __nv_bfloat16* cRowH(int z, int m) const { return Ch + ((size_t)z * C3_ + m) * HW_; }
    __device__ __nv_bfloat16* cRowL(int z, int m) const { return Cl + ((size_t)z * C3_ + m) * HW_; }
};
struct AvMap {
    const float* A; const __nv_bfloat16 *Bh, *Bl; __nv_bfloat16 *Ch, *Cl;
    static constexpr bool B_BF16 = true, C_BF16 = true;
    __device__ const float* aRow(int z, int m) const { return A + (size_t)z * (C_ * C_) + (size_t)m * C_; }
    __device__ const __nv_bfloat16* bRowH(int z, int k) const {
        int b = z >> 3, h = z & 7;
        return Bh + ((size_t)(b * C3_ + 2 * C_ + h * 24 + (k >> 3)) << 16) + ((k & 7) << 13);
    }
    __device__ const __nv_bfloat16* bRowL(int z, int k) const {
        int b = z >> 3, h = z & 7;
        return Bl + ((size_t)(b * C3_ + 2 * C_ + h * 24 + (k >> 3)) << 16) + ((k & 7) << 13);
    }
    __device__ __nv_bfloat16* cRowH(int z, int m) const {
        int b = z >> 3, h = z & 7;
        return Ch + ((size_t)(b * C_ + h * 24 + (m >> 3)) << 16) + ((m & 7) << 13);
    }
    __device__ __nv_bfloat16* cRowL(int z, int m) const {
        int b = z >> 3, h = z & 7;
        return Cl + ((size_t)(b * C_ + h * 24 + (m >> 3)) << 16) + ((m & 7) << 13);
    }
};
struct ProjMap {
    const float* A; const __nv_bfloat16 *Bh, *Bl; float* C;
    static constexpr bool B_BF16 = true, C_BF16 = false;
    __device__ const float* aRow(int z, int m) const { return A + (size_t)m * C_; }
    __device__ const __nv_bfloat16* bRowH(int z, int k) const { return Bh + ((size_t)z * C_ + k) * HW_; }
    __device__ const __nv_bfloat16* bRowL(int z, int k) const { return Bl + ((size_t)z * C_ + k) * HW_; }
    __device__ float* cRow(int z, int m) const { return C + ((size_t)z * C_ + m) * HW_; }
};

// =====================================================================
// bf16-split MMA GEMM: C[M,N] = A[M,K] @ B[K,N]
// BM=96, BN=128, BK=32, 256 threads, warp grid 2x4, warp tile 48x32.
// =====================================================================
template <class Map>
__global__ __launch_bounds__(256, 2) void gemm_mma(const Map map, const int K)
{
    __shared__ alignas(16) __nv_bfloat16 Ash[96][40];
    __shared__ alignas(16) __nv_bfloat16 Asl[96][40];
    __shared__ alignas(16) __nv_bfloat16 Bsh[32][136];
    __shared__ alignas(16) __nv_bfloat16 Bsl[32][136];

    const int z = blockIdx.z, bm = blockIdx.y * 96, bn = blockIdx.x * 128;
    const int tid = threadIdx.x, lane = tid & 31, w = tid >> 5;
    const int m0 = (w >> 2) * 48, n0 = (w & 3) * 32;

    // A stage slots (3 float4 per thread), pointers precomputed
    const float* apt[3]; int arow[3], ak4[3];
#pragma unroll
    for (int it = 0; it < 3; ++it) {
        int s = tid + it * 256; arow[it] = s >> 3; ak4[it] = s & 7;
        apt[it] = map.aRow(z, bm + arow[it]) + ak4[it] * 4;
    }

    float acc[3][4][4];
#pragma unroll
    for (int i = 0; i < 3; ++i)
#pragma unroll
        for (int j = 0; j < 4; ++j)
#pragma unroll
            for (int q = 0; q < 4; ++q) acc[i][j][q] = 0.f;

#pragma unroll 1
    for (int kt = 0; kt < K; kt += 32) {
        __syncthreads();
#pragma unroll
        for (int it = 0; it < 3; ++it) {
            float4 v = *(const float4*)(apt[it] + kt);
            stsplit(&Ash[arow[it]][ak4[it] * 4], &Asl[arow[it]][ak4[it] * 4], v);
        }
        if constexpr (Map::B_BF16) {
#pragma unroll
            for (int it = 0; it < 2; ++it) {
                int s = tid + it * 256; int row = s >> 4, c = s & 15;
                *(uint4*)&Bsh[row][c * 8] = *(const uint4*)(map.bRowH(z, kt + row) + bn + c * 8);
                *(uint4*)&Bsl[row][c * 8] = *(const uint4*)(map.bRowL(z, kt + row) + bn + c * 8);
            }
        } else {
#pragma unroll
            for (int it = 0; it < 4; ++it) {
                int s = tid + it * 256; int row = s >> 5, n4 = s & 31;
                float4 v = *(const float4*)(map.bRow(z, kt + row) + bn + n4 * 4);
                stsplit(&Bsh[row][n4 * 4], &Bsl[row][n4 * 4], v);
            }
        }
        __syncthreads();
#pragma unroll
        for (int kk = 0; kk < 32; kk += 16) {
            unsigned ah[3][4], al[3][4], bh[4][2], bl[4][2];
#pragma unroll
            for (int mi = 0; mi < 3; ++mi) {
                ldsm4(ah[mi], &Ash[m0 + mi * 16 + (lane & 15)][kk + (lane >> 4) * 8]);
                ldsm4(al[mi], &Asl[m0 + mi * 16 + (lane & 15)][kk + (lane >> 4) * 8]);
            }
#pragma unroll
            for (int ni = 0; ni < 4; ++ni) {
                ldsm2t(bh[ni], &Bsh[kk + (lane & 15)][n0 + ni * 8]);
                ldsm2t(bl[ni], &Bsl[kk + (lane & 15)][n0 + ni * 8]);
            }
#pragma unroll
            for (int mi = 0; mi < 3; ++mi)
#pragma unroll
                for (int ni = 0; ni < 4; ++ni) {
                    mma16816(acc[mi][ni], ah[mi], bh[ni]);
                    mma16816(acc[mi][ni], al[mi], bh[ni]);
                    mma16816(acc[mi][ni], ah[mi], bl[ni]);
                }
        }
    }

#pragma unroll
    for (int mi = 0; mi < 3; ++mi)
#pragma unroll
        for (int ni = 0; ni < 4; ++ni) {
            const int r = bm + m0 + mi * 16 + (lane >> 2);
            const int cc = bn + n0 + ni * 8 + (lane & 3) * 2;
            const float* a = acc[mi][ni];
            if constexpr (Map::C_BF16) {
                st_pair(map.cRowH(z, r) + cc,     map.cRowL(z, r) + cc,     a[0], a[1]);
                st_pair(map.cRowH(z, r + 8) + cc, map.cRowL(z, r + 8) + cc, a[2], a[3]);
            } else {
                *(float2*)(map.cRow(z, r) + cc)     = make_float2(a[0], a[1]);
                *(float2*)(map.cRow(z, r + 8) + cc) = make_float2(a[2], a[3]);
            }
        }
}

// =====================================================================
// Gram: C[i,j] = sum_n q[i,n]*k[j,n]  (A row-major over n, B "col-major")
// BM=BN=96, BK=32, split-K=8, warp tile 48x24.
// =====================================================================
__global__ __launch_bounds__(256, 2) void gram_mma(
    const __nv_bfloat16* __restrict__ dwh, const __nv_bfloat16* __restrict__ dwl,
    float* __restrict__ gramp)
{
    __shared__ alignas(16) __nv_bfloat16 Ash[96][40];
    __shared__ alignas(16) __nv_bfloat16 Asl[96][40];
    __shared__ alignas(16) __nv_bfloat16 Bsh[96][40];
    __shared__ alignas(16) __nv_bfloat16 Bsl[96][40];

    const int z = blockIdx.z;
    const int ks = z & 7, bh_ = z >> 3;
    const int h = bh_ & 7, b = bh_ >> 3;
    const int bi = blockIdx.y * 96, bj = blockIdx.x * 96;
    const int tid = threadIdx.x, lane = tid & 31, w = tid >> 5;
    const int m0 = (w >> 2) * 48, n0 = (w & 3) * 24;
    const int kbase = ks * 1024;

    const __nv_bfloat16 *qh[3], *ql[3], *kh[3], *kl[3];
    int srow[3], sc[3];
#pragma unroll
    for (int it = 0; it < 3; ++it) {
        int s = tid + it * 256; int row = s >> 3, c = s & 7;
        srow[it] = row; sc[it] = c;
        int qi = bi + row;
        size_t qoff = ((size_t)(b * C3_ + h * 24 + (qi >> 3)) << 16) + ((size_t)(qi & 7) << 13) + kbase + c * 4;
        qh[it] = dwh + qoff; ql[it] = dwl + qoff;
        int kj = bj + row;
        size_t koff = ((size_t)(b * C3_ + C_ + h * 24 + (kj >> 3)) << 16) + ((size_t)(kj & 7) << 13) + kbase + c * 4;
        kh[it] = dwh + koff; kl[it] = dwl + koff;
    }

    float acc[3][3][4];
#pragma unroll
    for (int i = 0; i < 3; ++i)
#pragma unroll
        for (int j = 0; j < 3; ++j)
#pragma unroll
            for (int q = 0; q < 4; ++q) acc[i][j][q] = 0.f;

#pragma unroll 1
    for (int kt = 0; kt < 1024; kt += 32) {
        __syncthreads();
#pragma unroll
        for (int it = 0; it < 3; ++it) {
            *(uint2*)&Ash[srow[it]][sc[it] * 4] = *(const uint2*)(qh[it] + kt);
            *(uint2*)&Asl[srow[it]][sc[it] * 4] = *(const uint2*)(ql[it] + kt);
            *(uint2*)&Bsh[srow[it]][sc[it] * 4] = *(const uint2*)(kh[it] + kt);
            *(uint2*)&Bsl[srow[it]][sc[it] * 4] = *(const uint2*)(kl[it] + kt);
        }
        __syncthreads();
#pragma unroll
        for (int kk = 0; kk < 32; kk += 16) {
            unsigned ah[3][4], al[3][4], bh2[3][2], bl2[3][2];
            const int l15 = lane & 15;
#pragma unroll
            for (int mi = 0; mi < 3; ++mi) {
                ldsm4(ah[mi], &Ash[m0 + mi * 16 + l15][kk + (lane >> 4) * 8]);
                ldsm4(al[mi], &Asl[m0 + mi * 16 + l15][kk + (lane >> 4) * 8]);
            }
#pragma unroll
            for (int ni = 0; ni < 3; ++ni) {
                ldsm2(bh2[ni], &Bsh[n0 + ni * 8 + (l15 & 7)][kk + (l15 >> 3) * 8]);
                ldsm2(bl2[ni], &Bsl[n0 + ni * 8 + (l15 & 7)][kk + (l15 >> 3) * 8]);
            }
#pragma unroll
            for (int mi = 0; mi < 3; ++mi)
#pragma unroll
                for (int ni = 0; ni < 3; ++ni) {
                    mma16816(acc[mi][ni], ah[mi], bh2[ni]);
                    mma16816(acc[mi][ni], al[mi], bh2[ni]);
                    mma16816(acc[mi][ni], ah[mi], bl2[ni]);
                }
        }
    }

    float* gp = gramp + ((size_t)ks * (B_ * HEADS_) + bh_) * (C_ * C_);
#pragma unroll
    for (int mi = 0; mi < 3; ++mi)
#pragma unroll
        for (int ni = 0; ni < 3; ++ni) {
            const int r = bi + m0 + mi * 16 + (lane >> 2);
            const int cc = bj + n0 + ni * 8 + (lane & 3) * 2;
            const float* a = acc[mi][ni];
            *(float2*)(gp + (size_t)r * C_ + cc)       = make_float2(a[0], a[1]);
            *(float2*)(gp + (size_t)(r + 8) * C_ + cc) = make_float2(a[2], a[3]);
        }
}

// ---------------- depthwise 3x3 (bf16 h/l in, bf16 h/l out) -------------------
__global__ __launch_bounds__(256) void dw_kernel(
    const __nv_bfloat16* __restrict__ inh, const __nv_bfloat16* __restrict__ inl,
    const float* __restrict__ dww,
    __nv_bfloat16* __restrict__ outh, __nv_bfloat16* __restrict__ outl)
{
    const int chg = blockIdx.z;            // b*576 + c
    const int c = chg % C3_;
    const size_t base = (size_t)chg << 16;

    float w[9];
#pragma unroll
    for (int i = 0; i < 9; ++i) w[i] = __ldg(&dww[c * 9 + i]);

    __shared__ float s[34][34];
    const int ox = blockIdx.x * 32 - 1, oy = blockIdx.y * 32 - 1;
    for (int t = threadIdx.x; t < 34 * 34; t += 256) {
        int lx = t % 34, ly = t / 34;
        int gx = ox + lx, gy = oy + ly;
        float v = 0.f;
        if ((unsigned)gx < W_ && (unsigned)gy < H_) {
            size_t idx = base + gy * W_ + gx;
            v = __bfloat162float(inh[idx]) + __bfloat162float(inl[idx]);
        }
        s[ly][lx] = v;
    }
    __syncthreads();

    const int tx = threadIdx.x & 31, ty0 = threadIdx.x >> 5;
#pragma unroll
    for (int r = 0; r < 4; ++r) {
        int ly = ty0 + 8 * r;
        float acc = s[ly + 0][tx + 0] * w[0] + s[ly + 0][tx + 1] * w[1] + s[ly + 0][tx + 2] * w[2]
                  + s[ly + 1][tx + 0] * w[3] + s[ly + 1][tx + 1] * w[4] + s[ly + 1][tx + 2] * w[5]
                  + s[ly + 2][tx + 0] * w[6] + s[ly + 2][tx + 1] * w[7] + s[ly + 2][tx + 2] * w[8];
        size_t idx = base + (size_t)(blockIdx.y * 32 + ly) * W_ + blockIdx.x * 32 + tx;
        __nv_bfloat16 hh = __float2bfloat16(acc);
        outh[idx] = hh;
        outl[idx] = __float2bfloat16(acc - __bfloat162float(hh));
    }
}

// ---------------- per-slice L2 norms of q and k -------------------------------
__global__ __launch_bounds__(256) void norms_kernel(
    const __nv_bfloat16* __restrict__ dwh, const __nv_bfloat16* __restrict__ dwl,
    float* __restrict__ invq, float* __restrict__ invk)
{
    const int z = blockIdx.x;              // b*192*8 + ch*8 + sl
    const int sl = z & 7;
    const int ch = (z >> 3) % C_;
    const int b = z / (C_ * 8);
    const size_t qoff = ((size_t)(b * C3_ + ch) << 16) + (sl << 13);
    const size_t koff = ((size_t)(b * C3_ + C_ + ch) << 16) + (sl << 13);
    const __nv_bfloat162* qh2 = (const __nv_bfloat162*)(dwh + qoff);
    const __nv_bfloat162* ql2 = (const __nv_bfloat162*)(dwl + qoff);
    const __nv_bfloat162* kh2 = (const __nv_bfloat162*)(dwh + koff);
    const __nv_bfloat162* kl2 = (const __nv_bfloat162*)(dwl + koff);

    float sq = 0.f, sk = 0.f;
    for (int t = threadIdx.x; t < 4096; t += 256) {
        __nv_bfloat162 h2 = qh2[t], l2 = ql2[t];
        float v0 = __bfloat162float(h2.x) + __bfloat162float(l2.x);
        float v1 = __bfloat162float(h2.y) + __bfloat162float(l2.y);
        sq += v0 * v0 + v1 * v1;
        h2 = kh2[t]; l2 = kl2[t];
        v0 = __bfloat162float(h2.x) + __bfloat162float(l2.x);
        v1 = __bfloat162float(h2.y) + __bfloat162float(l2.y);
        sk += v0 * v0 + v1 * v1;
    }
#pragma unroll
    for (int o = 16; o > 0; o >>= 1) {
        sq += __shfl_xor_sync(0xffffffffu, sq, o);
        sk += __shfl_xor_sync(0xffffffffu, sk, o);
    }
    __shared__ float r1[8], r2[8];
    if ((threadIdx.x & 31) == 0) { r1[threadIdx.x >> 5] = sq; r2[threadIdx.x >> 5] = sk; }
    __syncthreads();
    if (threadIdx.x == 0) {
        float a = 0.f, c2 = 0.f;
#pragma unroll
        for (int w2 = 0; w2 < 8; ++w2) { a += r1[w2]; c2 += r2[w2]; }
        int idx = (b * C_ + ch) * 8 + sl;
        invq[idx] = 1.f / fmaxf(sqrtf(a), 1e-12f);
        invk[idx] = 1.f / fmaxf(sqrtf(c2), 1e-12f);
    }
}

// ---------------- split-K reduce + normalize scales + softmax -----------------
__global__ void softmax_kernel(
    const float* __restrict__ gramp, const float* __restrict__ invq,
    const float* __restrict__ invk, const float* __restrict__ temp,
    float* __restrict__ attn)
{
    const int i = blockIdx.x % C_;
    const int bh = blockIdx.x / C_;
    const int head = bh & 7, b = bh >> 3;
    const int j = threadIdx.x;              // 192 threads

    const long long base = (long long)bh * (C_ * C_) + i * C_ + j;
    float s = 0.f;
#pragma unroll
    for (int ks = 0; ks < KSPLIT_; ++ks)
        s += gramp[(long long)ks * (B_ * HEADS_ * C_ * C_) + base];

    s *= invq[(b * C_ + head * 24 + (i >> 3)) * 8 + (i & 7)]
       * invk[(b * C_ + head * 24 + (j >> 3)) * 8 + (j & 7)]
       * temp[head];

    __shared__ float red[8];
    float m = s;
#pragma unroll
    for (int o = 16; o > 0; o >>= 1) m = fmaxf(m, __shfl_xor_sync(0xffffffffu, m, o));
    if ((threadIdx.x & 31) == 0) red[threadIdx.x >> 5] = m;
    __syncthreads();
    m = fmaxf(fmaxf(fmaxf(red[0], red[1]), fmaxf(red[2], red[3])), fmaxf(red[4], red[5]));

    float p = expf(s - m);
    float sum = p;
#pragma unroll
    for (int o = 16; o > 0; o >>= 1) sum += __shfl_xor_sync(0xffffffffu, sum, o);
    __syncthreads();
    if ((threadIdx.x & 31) == 0) red[threadIdx.x >> 5] = sum;
    __syncthreads();
    sum = red[0] + red[1] + red[2] + red[3] + red[4] + red[5];

    attn[base] = p / sum;
}

// ---------------- launch -------------------------------------------------------
extern "C" void kernel_launch(void* const* d_in, const int* in_sizes, int n_in,
                              void* d_out, int out_size)
{
    const float* x      = (const float*)d_in[0];
    const float* qkv_w  = (const float*)d_in[1];
    const float* dw_w   = (const float*)d_in[2];
    const float* proj_w = (const float*)d_in[3];
    const float* temp   = (const float*)d_in[4];
    float* out = (float*)d_out;

    __nv_bfloat16 *qkvh, *qkvl, *dwh, *dwl, *avh, *avl;
    float *gramp, *attn, *invq, *invk;
    cudaGetSymbolAddress((void**)&qkvh, g_qkvh);
    cudaGetSymbolAddress((void**)&qkvl, g_qkvl);
    cudaGetSymbolAddress((void**)&dwh,  g_dwh);
    cudaGetSymbolAddress((void**)&dwl,  g_dwl);
    cudaGetSymbolAddress((void**)&avh,  g_avh);
    cudaGetSymbolAddress((void**)&avl,  g_avl);
    cudaGetSymbolAddress((void**)&gramp, g_gramp);
    cudaGetSymbolAddress((void**)&attn,  g_attn);
    cudaGetSymbolAddress((void**)&invq,  g_invq);
    cudaGetSymbolAddress((void**)&invk,  g_invk);

    // 1) qkv = qkv_w @ x  -> bf16 hi/lo
    {
        QkvMap m{qkv_w, x, qkvh, qkvl};
        gemm_mma<QkvMap><<<dim3(HW_ / 128, C3_ / 96, B_), 256>>>(m, C_);
    }
    // 2) depthwise 3x3
    dw_kernel<<<dim3(W_ / 32, H_ / 32, B_ * C3_), 256>>>(qkvh, qkvl, dw_w, dwh, dwl);
    // 3) norms
    norms_kernel<<<B_ * C_ * 8, 256>>>(dwh, dwl, invq, invk);
    // 4) gram partials (split-K = 8)
    gram_mma<<<dim3(2, 2, B_ * HEADS_ * KSPLIT_), 256>>>(dwh, dwl, gramp);
    // 5) softmax
    softmax_kernel<<<B_ * HEADS_ * C_, C_>>>(gramp, invq, invk, temp, attn);
    // 6) attn @ v -> bf16 hi/lo
    {
        AvMap m{attn, dwh, dwl, avh, avl};
        gemm_mma<AvMap><<<dim3(HW_ / HEADS_ / 128, C_ / 96, B_ * HEADS_), 256>>>(m, C_);
    }
    // 7) out = proj_w @ av
    {
        ProjMap m{proj_w, avh, avl, out};
        gemm_mma<ProjMap><<<dim3(HW_ / 128, C_ / 96, B_), 256>>>(m, C_);
    }
}

// round 4
// speedup vs baseline: 2.3051x; 1.0885x over previous
#include <cuda_runtime.h>
#include <cuda_bf16.h>
#include <cstdint>

#define B_      2
#define C_      192
#define C3_     576
#define H_      256
#define W_      256
#define HW_     65536
#define HEADS_  8
#define KSPLIT_ 8

// ---------------- scratch (device globals: allocation-free rule) ----------------
__device__ __nv_bfloat16 g_xh  [(size_t)B_ * C_ * HW_];
__device__ __nv_bfloat16 g_xl  [(size_t)B_ * C_ * HW_];
__device__ __nv_bfloat16 g_wqh [C3_ * C_];
__device__ __nv_bfloat16 g_wql [C3_ * C_];
__device__ __nv_bfloat16 g_wph [C_ * C_];
__device__ __nv_bfloat16 g_wpl [C_ * C_];
__device__ __nv_bfloat16 g_qkvh[(size_t)B_ * C3_ * HW_];
__device__ __nv_bfloat16 g_qkvl[(size_t)B_ * C3_ * HW_];
__device__ __nv_bfloat16 g_dwh [(size_t)B_ * C3_ * HW_];
__device__ __nv_bfloat16 g_dwl [(size_t)B_ * C3_ * HW_];
__device__ __nv_bfloat16 g_avh [(size_t)B_ * C_ * HW_];
__device__ __nv_bfloat16 g_avl [(size_t)B_ * C_ * HW_];
__device__ float g_gramp[(size_t)KSPLIT_ * B_ * HEADS_ * C_ * C_];
__device__ __nv_bfloat16 g_attnh[(size_t)B_ * HEADS_ * C_ * C_];
__device__ __nv_bfloat16 g_attnl[(size_t)B_ * HEADS_ * C_ * C_];
__device__ float g_partq[B_ * C_ * 8 * 8];
__device__ float g_partk[B_ * C_ * 8 * 8];
__device__ float g_invq [B_ * C_ * 8];
__device__ float g_invk [B_ * C_ * 8];

// ---------------- mma / ldmatrix / cp.async helpers ----------------
__device__ __forceinline__ void ldsm4(unsigned* r, const void* p) {
    unsigned a = (unsigned)__cvta_generic_to_shared(p);
    asm volatile("ldmatrix.sync.aligned.m8n8.x4.shared.b16 {%0,%1,%2,%3}, [%4];"
                 : "=r"(r[0]), "=r"(r[1]), "=r"(r[2]), "=r"(r[3]) : "r"(a));
}
__device__ __forceinline__ void ldsm2t(unsigned* r, const void* p) {
    unsigned a = (unsigned)__cvta_generic_to_shared(p);
    asm volatile("ldmatrix.sync.aligned.m8n8.x2.trans.shared.b16 {%0,%1}, [%2];"
                 : "=r"(r[0]), "=r"(r[1]) : "r"(a));
}
__device__ __forceinline__ void ldsm2(unsigned* r, const void* p) {
    unsigned a = (unsigned)__cvta_generic_to_shared(p);
    asm volatile("ldmatrix.sync.aligned.m8n8.x2.shared.b16 {%0,%1}, [%2];"
                 : "=r"(r[0]), "=r"(r[1]) : "r"(a));
}
__device__ __forceinline__ void mma16816(float* c, const unsigned* a, const unsigned* b) {
    asm volatile("mma.sync.aligned.m16n8k16.row.col.f32.bf16.bf16.f32 "
                 "{%0,%1,%2,%3},{%4,%5,%6,%7},{%8,%9},{%0,%1,%2,%3};"
                 : "+f"(c[0]), "+f"(c[1]), "+f"(c[2]), "+f"(c[3])
                 : "r"(a[0]), "r"(a[1]), "r"(a[2]), "r"(a[3]), "r"(b[0]), "r"(b[1]));
}
__device__ __forceinline__ void cpa16(unsigned dst, const void* src) {
    asm volatile("cp.async.cg.shared.global [%0], [%1], 16;\n" :: "r"(dst), "l"(src));
}
#define CP_COMMIT() asm volatile("cp.async.commit_group;\n")
#define CP_WAIT0()  asm volatile("cp.async.wait_group 0;\n")

__device__ __forceinline__ void stsplit(__nv_bfloat16* ph, __nv_bfloat16* pl, float4 v) {
    __nv_bfloat16 h0 = __float2bfloat16(v.x), h1 = __float2bfloat16(v.y);
    __nv_bfloat16 h2 = __float2bfloat16(v.z), h3 = __float2bfloat16(v.w);
    __nv_bfloat162 t;
    t.x = h0; t.y = h1; ((__nv_bfloat162*)ph)[0] = t;
    t.x = h2; t.y = h3; ((__nv_bfloat162*)ph)[1] = t;
    t.x = __float2bfloat16(v.x - __bfloat162float(h0));
    t.y = __float2bfloat16(v.y - __bfloat162float(h1)); ((__nv_bfloat162*)pl)[0] = t;
    t.x = __float2bfloat16(v.z - __bfloat162float(h2));
    t.y = __float2bfloat16(v.w - __bfloat162float(h3)); ((__nv_bfloat162*)pl)[1] = t;
}
__device__ __forceinline__ void st_pair(__nv_bfloat16* ph, __nv_bfloat16* pl, float x, float y) {
    __nv_bfloat16 hx = __float2bfloat16(x), hy = __float2bfloat16(y);
    __nv_bfloat162 hp; hp.x = hx; hp.y = hy; *(__nv_bfloat162*)ph = hp;
    __nv_bfloat162 lp;
    lp.x = __float2bfloat16(x - __bfloat162float(hx));
    lp.y = __float2bfloat16(y - __bfloat162float(hy));
    *(__nv_bfloat162*)pl = lp;
}

// ---------------- fp32 -> bf16 hi/lo split (elementwise) ----------------
__global__ __launch_bounds__(256) void split_kernel(
    const float* __restrict__ in, __nv_bfloat16* __restrict__ oh,
    __nv_bfloat16* __restrict__ ol, int n)
{
    int i = (blockIdx.x * 256 + threadIdx.x) * 4;
    if (i < n) {
        float4 v = *(const float4*)(in + i);
        stsplit(oh + i, ol + i, v);
    }
}

// ---------------- maps ----------------
struct QkvMap {
    const __nv_bfloat16 *Ah, *Al, *Bh, *Bl; __nv_bfloat16 *Ch, *Cl;
    static constexpr bool C_BF16 = true;
    static constexpr size_t BSTRIDE32 = (size_t)32 * HW_;
    __device__ const __nv_bfloat16* aRowH(int z, int m) const { return Ah + (size_t)m * C_; }
    __device__ const __nv_bfloat16* aRowL(int z, int m) const { return Al + (size_t)m * C_; }
    __device__ const __nv_bfloat16* bRowH(int z, int k) const { return Bh + ((size_t)z * C_ + k) * HW_; }
    __device__ const __nv_bfloat16* bRowL(int z, int k) const { return Bl + ((size_t)z * C_ + k) * HW_; }
    __device__ __nv_bfloat16* cRowH(int z, int m) const { return Ch + ((size_t)z * C3_ + m) * HW_; }
    __device__ __nv_bfloat16* cRowL(int z, int m) const { return Cl + ((size_t)z * C3_ + m) * HW_; }
};
struct AvMap {
    const __nv_bfloat16 *Ah, *Al, *Bh, *Bl; __nv_bfloat16 *Ch, *Cl;
    static constexpr bool C_BF16 = true;
    static constexpr size_t BSTRIDE32 = (size_t)4 << 16;
    __device__ const __nv_bfloat16* aRowH(int z, int m) const { return Ah + (size_t)z * (C_ * C_) + (size_t)m * C_; }
    __device__ const __nv_bfloat16* aRowL(int z, int m) const { return Al + (size_t)z * (C_ * C_) + (size_t)m * C_; }
    __device__ const __nv_bfloat16* bRowH(int z, int k) const {
        int b = z >> 3, h = z & 7;
        return Bh + ((size_t)(b * C3_ + 2 * C_ + h * 24 + (k >> 3)) << 16) + ((k & 7) << 13);
    }
    __device__ const __nv_bfloat16* bRowL(int z, int k) const {
        int b = z >> 3, h = z & 7;
        return Bl + ((size_t)(b * C3_ + 2 * C_ + h * 24 + (k >> 3)) << 16) + ((k & 7) << 13);
    }
    __device__ __nv_bfloat16* cRowH(int z, int m) const {
        int b = z >> 3, h = z & 7;
        return Ch + ((size_t)(b * C_ + h * 24 + (m >> 3)) << 16) + ((m & 7) << 13);
    }
    __device__ __nv_bfloat16* cRowL(int z, int m) const {
        int b = z >> 3, h = z & 7;
        return Cl + ((size_t)(b * C_ + h * 24 + (m >> 3)) << 16) + ((m & 7) << 13);
    }
};
struct ProjMap {
    const __nv_bfloat16 *Ah, *Al, *Bh, *Bl; float* C;
    static constexpr bool C_BF16 = false;
    static constexpr size_t BSTRIDE32 = (size_t)32 * HW_;
    __device__ const __nv_bfloat16* aRowH(int z, int m) const { return Ah + (size_t)m * C_; }
    __device__ const __nv_bfloat16* aRowL(int z, int m) const { return Al + (size_t)m * C_; }
    __device__ const __nv_bfloat16* bRowH(int z, int k) const { return Bh + ((size_t)z * C_ + k) * HW_; }
    __device__ const __nv_bfloat16* bRowL(int z, int k) const { return Bl + ((size_t)z * C_ + k) * HW_; }
    __device__ float* cRow(int z, int m) const { return C + ((size_t)z * C_ + m) * HW_; }
};

// =====================================================================
// bf16-split MMA GEMM, BM=96 BN=128 BK=32, cp.async 2-stage pipeline.
// =====================================================================
template <class Map>
__global__ __launch_bounds__(256, 2) void gemm_mma(const Map map, const int K)
{
    __shared__ alignas(16) __nv_bfloat16 Ash[2][96][40];
    __shared__ alignas(16) __nv_bfloat16 Asl[2][96][40];
    __shared__ alignas(16) __nv_bfloat16 Bsh[2][32][136];
    __shared__ alignas(16) __nv_bfloat16 Bsl[2][32][136];
    constexpr unsigned ASTG = 96 * 40 * 2;
    constexpr unsigned BSTG = 32 * 136 * 2;

    const int z = blockIdx.z, bm = blockIdx.y * 96, bn = blockIdx.x * 128;
    const int tid = threadIdx.x, lane = tid & 31, w = tid >> 5;
    const int m0 = (w >> 2) * 48, n0 = (w & 3) * 32;

    // loader chunk maps (16B each): A 768 chunks, B 1024 chunks
    const __nv_bfloat16* asrc[3]; unsigned adst[3];
#pragma unroll
    for (int it = 0; it < 3; ++it) {
        int idx = tid + it * 256;
        int which = idx / 384, w2 = idx % 384;
        int row = w2 >> 2, c4 = w2 & 3;
        const __nv_bfloat16* base = which ? map.aRowL(z, bm + row) : map.aRowH(z, bm + row);
        asrc[it] = base + c4 * 8;
        adst[it] = (unsigned)__cvta_generic_to_shared(which ? &Asl[0][row][c4 * 8] : &Ash[0][row][c4 * 8]);
    }
    const __nv_bfloat16* bsrc[4]; unsigned bdst[4];
#pragma unroll
    for (int it = 0; it < 4; ++it) {
        int idx = tid + it * 256;
        int which = idx >> 9, w2 = idx & 511;
        int row = w2 >> 4, c4 = w2 & 15;
        const __nv_bfloat16* base = which ? map.bRowL(z, row) : map.bRowH(z, row);
        bsrc[it] = base + bn + c4 * 8;
        bdst[it] = (unsigned)__cvta_generic_to_shared(which ? &Bsl[0][row][c4 * 8] : &Bsh[0][row][c4 * 8]);
    }

    float acc[3][4][4];
#pragma unroll
    for (int i = 0; i < 3; ++i)
#pragma unroll
        for (int j = 0; j < 4; ++j)
#pragma unroll
            for (int q = 0; q < 4; ++q) acc[i][j][q] = 0.f;

    const int nStage = K >> 5;
    // prologue: stage 0 -> buf 0
    {
#pragma unroll
        for (int it = 0; it < 3; ++it) cpa16(adst[it], asrc[it]);
#pragma unroll
        for (int it = 0; it < 4; ++it) cpa16(bdst[it], bsrc[it]);
        CP_COMMIT();
    }
    int buf = 0;
#pragma unroll 1
    for (int s = 0; s < nStage; ++s) {
        CP_WAIT0();
        __syncthreads();
        if (s + 1 < nStage) {
            const unsigned ao = (buf ^ 1) * ASTG, bo = (buf ^ 1) * BSTG;
            const int ka = (s + 1) * 32;
            const size_t kb = (size_t)(s + 1) * Map::BSTRIDE32;
#pragma unroll
            for (int it = 0; it < 3; ++it) cpa16(adst[it] + ao, asrc[it] + ka);
#pragma unroll
            for (int it = 0; it < 4; ++it) cpa16(bdst[it] + bo, bsrc[it] + kb);
            CP_COMMIT();
        }
#pragma unroll
        for (int kk = 0; kk < 32; kk += 16) {
            unsigned ah[3][4], al[3][4], bh[4][2], bl[4][2];
#pragma unroll
            for (int mi = 0; mi < 3; ++mi) {
                ldsm4(ah[mi], &Ash[buf][m0 + mi * 16 + (lane & 15)][kk + (lane >> 4) * 8]);
                ldsm4(al[mi], &Asl[buf][m0 + mi * 16 + (lane & 15)][kk + (lane >> 4) * 8]);
            }
#pragma unroll
            for (int ni = 0; ni < 4; ++ni) {
                ldsm2t(bh[ni], &Bsh[buf][kk + (lane & 15)][n0 + ni * 8]);
                ldsm2t(bl[ni], &Bsl[buf][kk + (lane & 15)][n0 + ni * 8]);
            }
#pragma unroll
            for (int mi = 0; mi < 3; ++mi)
#pragma unroll
                for (int ni = 0; ni < 4; ++ni) {
                    mma16816(acc[mi][ni], ah[mi], bh[ni]);
                    mma16816(acc[mi][ni], al[mi], bh[ni]);
                    mma16816(acc[mi][ni], ah[mi], bl[ni]);
                }
        }
        buf ^= 1;
    }

#pragma unroll
    for (int mi = 0; mi < 3; ++mi)
#pragma unroll
        for (int ni = 0; ni < 4; ++ni) {
            const int r = bm + m0 + mi * 16 + (lane >> 2);
            const int cc = bn + n0 + ni * 8 + (lane & 3) * 2;
            const float* a = acc[mi][ni];
            if constexpr (Map::C_BF16) {
                st_pair(map.cRowH(z, r) + cc,     map.cRowL(z, r) + cc,     a[0], a[1]);
                st_pair(map.cRowH(z, r + 8) + cc, map.cRowL(z, r + 8) + cc, a[2], a[3]);
            } else {
                *(float2*)(map.cRow(z, r) + cc)     = make_float2(a[0], a[1]);
                *(float2*)(map.cRow(z, r + 8) + cc) = make_float2(a[2], a[3]);
            }
        }
}

// =====================================================================
// Gram (q @ k^T), BM=BN=96 BK=32, split-K=8, cp.async 2-stage pipeline.
// =====================================================================
__global__ __launch_bounds__(256, 2) void gram_mma(
    const __nv_bfloat16* __restrict__ dwh, const __nv_bfloat16* __restrict__ dwl,
    float* __restrict__ gramp)
{
    __shared__ alignas(16) __nv_bfloat16 Ash[2][96][40];
    __shared__ alignas(16) __nv_bfloat16 Asl[2][96][40];
    __shared__ alignas(16) __nv_bfloat16 Bsh[2][96][40];
    __shared__ alignas(16) __nv_bfloat16 Bsl[2][96][40];
    constexpr unsigned STG = 96 * 40 * 2;

    const int z = blockIdx.z;
    const int ks = z & 7, bh_ = z >> 3;
    const int h = bh_ & 7, b = bh_ >> 3;
    const int bi = blockIdx.y * 96, bj = blockIdx.x * 96;
    const int tid = threadIdx.x, lane = tid & 31, w = tid >> 5;
    const int m0 = (w >> 2) * 48, n0 = (w & 3) * 24;
    const int kbase = ks * 1024;

    // 1536 chunks of 16B: which 0=qh 1=ql 2=kh 3=kl
    const __nv_bfloat16* src[6]; unsigned dst[6];
#pragma unroll
    for (int it = 0; it < 6; ++it) {
        int idx = tid + it * 256;
        int which = idx / 384, w2 = idx % 384;
        int row = w2 >> 2, c4 = w2 & 3;
        size_t off;
        if (which < 2) { int qi = bi + row; off = ((size_t)(b * C3_ + h * 24 + (qi >> 3)) << 16) + ((size_t)(qi & 7) << 13); }
        else           { int kj = bj + row; off = ((size_t)(b * C3_ + C_ + h * 24 + (kj >> 3)) << 16) + ((size_t)(kj & 7) << 13); }
        src[it] = ((which & 1) ? dwl : dwh) + off + kbase + c4 * 8;
        __nv_bfloat16* d;
        if      (which == 0) d = &Ash[0][row][c4 * 8];
        else if (which == 1) d = &Asl[0][row][c4 * 8];
        else if (which == 2) d = &Bsh[0][row][c4 * 8];
        else                 d = &Bsl[0][row][c4 * 8];
        dst[it] = (unsigned)__cvta_generic_to_shared(d);
    }

    float acc[3][3][4];
#pragma unroll
    for (int i = 0; i < 3; ++i)
#pragma unroll
        for (int j = 0; j < 3; ++j)
#pragma unroll
            for (int q = 0; q < 4; ++q) acc[i][j][q] = 0.f;

    {
#pragma unroll
        for (int it = 0; it < 6; ++it) cpa16(dst[it], src[it]);
        CP_COMMIT();
    }
    int buf = 0;
#pragma unroll 1
    for (int s = 0; s < 32; ++s) {               // K = 1024
        CP_WAIT0();
        __syncthreads();
        if (s + 1 < 32) {
            const unsigned o = (buf ^ 1) * STG;
            const int ka = (s + 1) * 32;
#pragma unroll
            for (int it = 0; it < 6; ++it) cpa16(dst[it] + o, src[it] + ka);
            CP_COMMIT();
        }
#pragma unroll
        for (int kk = 0; kk < 32; kk += 16) {
            unsigned ah[3][4], al[3][4], bh2[3][2], bl2[3][2];
            const int l15 = lane & 15;
#pragma unroll
            for (int mi = 0; mi < 3; ++mi) {
                ldsm4(ah[mi], &Ash[buf][m0 + mi * 16 + l15][kk + (lane >> 4) * 8]);
                ldsm4(al[mi], &Asl[buf][m0 + mi * 16 + l15][kk + (lane >> 4) * 8]);
            }
#pragma unroll
            for (int ni = 0; ni < 3; ++ni) {
                ldsm2(bh2[ni], &Bsh[buf][n0 + ni * 8 + (l15 & 7)][kk + (l15 >> 3) * 8]);
                ldsm2(bl2[ni], &Bsl[buf][n0 + ni * 8 + (l15 & 7)][kk + (l15 >> 3) * 8]);
            }
#pragma unroll
            for (int mi = 0; mi < 3; ++mi)
#pragma unroll
                for (int ni = 0; ni < 3; ++ni) {
                    mma16816(acc[mi][ni], ah[mi], bh2[ni]);
                    mma16816(acc[mi][ni], al[mi], bh2[ni]);
                    mma16816(acc[mi][ni], ah[mi], bl2[ni]);
                }
        }
        buf ^= 1;
    }

    float* gp = gramp + ((size_t)ks * (B_ * HEADS_) + bh_) * (C_ * C_);
#pragma unroll
    for (int mi = 0; mi < 3; ++mi)
#pragma unroll
        for (int ni = 0; ni < 3; ++ni) {
            const int r = bi + m0 + mi * 16 + (lane >> 2);
            const int cc = bj + n0 + ni * 8 + (lane & 3) * 2;
            const float* a = acc[mi][ni];
            *(float2*)(gp + (size_t)r * C_ + cc)       = make_float2(a[0], a[1]);
            *(float2*)(gp + (size_t)(r + 8) * C_ + cc) = make_float2(a[2], a[3]);
        }
}

// ---------------- depthwise 3x3 + fused q/k norm partials ---------------------
__global__ __launch_bounds__(256) void dw_kernel(
    const __nv_bfloat16* __restrict__ inh, const __nv_bfloat16* __restrict__ inl,
    const float* __restrict__ dww,
    __nv_bfloat16* __restrict__ outh, __nv_bfloat16* __restrict__ outl,
    float* __restrict__ partq, float* __restrict__ partk)
{
    const int chg = blockIdx.z;            // b*576 + c
    const int c = chg % C3_;
    const int b = chg / C3_;
    const size_t base = (size_t)chg << 16;

    float w[9];
#pragma unroll
    for (int i = 0; i < 9; ++i) w[i] = __ldg(&dww[c * 9 + i]);

    __shared__ float s[34][34];
    const int ox = blockIdx.x * 32 - 1, oy = blockIdx.y * 32 - 1;
    for (int t = threadIdx.x; t < 34 * 34; t += 256) {
        int lx = t % 34, ly = t / 34;
        int gx = ox + lx, gy = oy + ly;
        float v = 0.f;
        if ((unsigned)gx < W_ && (unsigned)gy < H_) {
            size_t idx = base + gy * W_ + gx;
            v = __bfloat162float(inh[idx]) + __bfloat162float(inl[idx]);
        }
        s[ly][lx] = v;
    }
    __syncthreads();

    const int tx = threadIdx.x & 31, ty0 = threadIdx.x >> 5;
    float ss = 0.f;
#pragma unroll
    for (int r = 0; r < 4; ++r) {
        int ly = ty0 + 8 * r;
        float acc = s[ly + 0][tx + 0] * w[0] + s[ly + 0][tx + 1] * w[1] + s[ly + 0][tx + 2] * w[2]
                  + s[ly + 1][tx + 0] * w[3] + s[ly + 1][tx + 1] * w[4] + s[ly + 1][tx + 2] * w[5]
                  + s[ly + 2][tx + 0] * w[6] + s[ly + 2][tx + 1] * w[7] + s[ly + 2][tx + 2] * w[8];
        ss += acc * acc;
        size_t idx = base + (size_t)(blockIdx.y * 32 + ly) * W_ + blockIdx.x * 32 + tx;
        __nv_bfloat16 hh = __float2bfloat16(acc);
        outh[idx] = hh;
        outl[idx] = __float2bfloat16(acc - __bfloat162float(hh));
    }

    if (c < 2 * C_) {
        __shared__ float red[8];
#pragma unroll
        for (int o = 16; o > 0; o >>= 1) ss += __shfl_xor_sync(0xffffffffu, ss, o);
        if ((threadIdx.x & 31) == 0) red[threadIdx.x >> 5] = ss;
        __syncthreads();
        if (threadIdx.x == 0) {
            float tot = 0.f;
#pragma unroll
            for (int i = 0; i < 8; ++i) tot += red[i];
            // dw block (bx,by) covers spatial rows [by*32,by*32+32) == slice by
            if (c < C_)
                partq[((b * C_ + c) * 8 + blockIdx.y) * 8 + blockIdx.x] = tot;
            else
                partk[((b * C_ + (c - C_)) * 8 + blockIdx.y) * 8 + blockIdx.x] = tot;
        }
    }
}

__global__ void norms_finish(
    const float* __restrict__ partq, const float* __restrict__ partk,
    float* __restrict__ invq, float* __restrict__ invk)
{
    int idx = blockIdx.x * blockDim.x + threadIdx.x;
    if (idx < B_ * C_ * 8) {
        float sq = 0.f, sk = 0.f;
#pragma unroll
        for (int i = 0; i < 8; ++i) { sq += partq[idx * 8 + i]; sk += partk[idx * 8 + i]; }
        invq[idx] = 1.f / fmaxf(sqrtf(sq), 1e-12f);
        invk[idx] = 1.f / fmaxf(sqrtf(sk), 1e-12f);
    }
}

// ---------------- split-K reduce + scale + softmax -> bf16 h/l ---------------
__global__ void softmax_kernel(
    const float* __restrict__ gramp, const float* __restrict__ invq,
    const float* __restrict__ invk, const float* __restrict__ temp,
    __nv_bfloat16* __restrict__ attnh, __nv_bfloat16* __restrict__ attnl)
{
    const int i = blockIdx.x % C_;
    const int bh = blockIdx.x / C_;
    const int head = bh & 7, b = bh >> 3;
    const int j = threadIdx.x;              // 192 threads

    const long long base = (long long)bh * (C_ * C_) + i * C_ + j;
    float s = 0.f;
#pragma unroll
    for (int ks = 0; ks < KSPLIT_; ++ks)
        s += gramp[(long long)ks * (B_ * HEADS_ * C_ * C_) + base];

    s *= invq[(b * C_ + head * 24 + (i >> 3)) * 8 + (i & 7)]
       * invk[(b * C_ + head * 24 + (j >> 3)) * 8 + (j & 7)]
       * temp[head];

    __shared__ float red[8];
    float m = s;
#pragma unroll
    for (int o = 16; o > 0; o >>= 1) m = fmaxf(m, __shfl_xor_sync(0xffffffffu, m, o));
    if ((threadIdx.x & 31) == 0) red[threadIdx.x >> 5] = m;
    __syncthreads();
    m = fmaxf(fmaxf(fmaxf(red[0], red[1]), fmaxf(red[2], red[3])), fmaxf(red[4], red[5]));

    float p = expf(s - m);
    float sum = p;
#pragma unroll
    for (int o = 16; o > 0; o >>= 1) sum += __shfl_xor_sync(0xffffffffu, sum, o);
    __syncthreads();
    if ((threadIdx.x & 31) == 0) red[threadIdx.x >> 5] = sum;
    __syncthreads();
    sum = red[0] + red[1] + red[2] + red[3] + red[4] + red[5];

    float v = p / sum;
    __nv_bfloat16 hh = __float2bfloat16(v);
    attnh[base] = hh;
    attnl[base] = __float2bfloat16(v - __bfloat162float(hh));
}

// ---------------- launch -------------------------------------------------------
extern "C" void kernel_launch(void* const* d_in, const int* in_sizes, int n_in,
                              void* d_out, int out_size)
{
    const float* x      = (const float*)d_in[0];
    const float* qkv_w  = (const float*)d_in[1];
    const float* dw_w   = (const float*)d_in[2];
    const float* proj_w = (const float*)d_in[3];
    const float* temp   = (const float*)d_in[4];
    float* out = (float*)d_out;

    __nv_bfloat16 *xh, *xl, *wqh, *wql, *wph, *wpl;
    __nv_bfloat16 *qkvh, *qkvl, *dwh, *dwl, *avh, *avl, *attnh, *attnl;
    float *gramp, *partq, *partk, *invq, *invk;
    cudaGetSymbolAddress((void**)&xh,   g_xh);
    cudaGetSymbolAddress((void**)&xl,   g_xl);
    cudaGetSymbolAddress((void**)&wqh,  g_wqh);
    cudaGetSymbolAddress((void**)&wql,  g_wql);
    cudaGetSymbolAddress((void**)&wph,  g_wph);
    cudaGetSymbolAddress((void**)&wpl,  g_wpl);
    cudaGetSymbolAddress((void**)&qkvh, g_qkvh);
    cudaGetSymbolAddress((void**)&qkvl, g_qkvl);
    cudaGetSymbolAddress((void**)&dwh,  g_dwh);
    cudaGetSymbolAddress((void**)&dwl,  g_dwl);
    cudaGetSymbolAddress((void**)&avh,  g_avh);
    cudaGetSymbolAddress((void**)&avl,  g_avl);
    cudaGetSymbolAddress((void**)&attnh, g_attnh);
    cudaGetSymbolAddress((void**)&attnl, g_attnl);
    cudaGetSymbolAddress((void**)&gramp, g_gramp);
    cudaGetSymbolAddress((void**)&partq, g_partq);
    cudaGetSymbolAddress((void**)&partk, g_partk);
    cudaGetSymbolAddress((void**)&invq,  g_invq);
    cudaGetSymbolAddress((void**)&invk,  g_invk);

    // 0) pre-split fp32 operands into bf16 hi/lo
    split_kernel<<<(B_ * C_ * HW_ / 4 + 255) / 256, 256>>>(x, xh, xl, B_ * C_ * HW_);
    split_kernel<<<(C3_ * C_ / 4 + 255) / 256, 256>>>(qkv_w, wqh, wql, C3_ * C_);
    split_kernel<<<(C_ * C_ / 4 + 255) / 256, 256>>>(proj_w, wph, wpl, C_ * C_);

    // 1) qkv = qkv_w @ x
    {
        QkvMap m{wqh, wql, xh, xl, qkvh, qkvl};
        gemm_mma<QkvMap><<<dim3(HW_ / 128, C3_ / 96, B_), 256>>>(m, C_);
    }
    // 2) depthwise 3x3 + fused norm partials
    dw_kernel<<<dim3(W_ / 32, H_ / 32, B_ * C3_), 256>>>(qkvh, qkvl, dw_w, dwh, dwl, partq, partk);
    // 3) finish norms
    norms_finish<<<(B_ * C_ * 8 + 255) / 256, 256>>>(partq, partk, invq, invk);
    // 4) gram partials (split-K = 8)
    gram_mma<<<dim3(2, 2, B_ * HEADS_ * KSPLIT_), 256>>>(dwh, dwl, gramp);
    // 5) softmax -> bf16 h/l attn
    softmax_kernel<<<B_ * HEADS_ * C_, C_>>>(gramp, invq, invk, temp, attnh, attnl);
    // 6) attn @ v
    {
        AvMap m{attnh, attnl, dwh, dwl, avh, avl};
        gemm_mma<AvMap><<<dim3(HW_ / HEADS_ / 128, C_ / 96, B_ * HEADS_), 256>>>(m, C_);
    }
    // 7) out = proj_w @ av
    {
        ProjMap m{wph, wpl, avh, avl, out};
        gemm_mma<ProjMap><<<dim3(HW_ / 128, C_ / 96, B_), 256>>>(m, C_);
    }
}